// round 2
// baseline (speedup 1.0000x reference)
#include <cuda_runtime.h>
#include <cuda_bf16.h>
#include <cstdint>
#include <cstdio>

#define N_NODES 100000
#define N_EDGES 1600000
#define T_STEPS 12

// ----------------- static device scratch (no allocations allowed) -----------------
__device__ float g_agg[(size_t)N_NODES * 128];
__device__ float g_h0 [(size_t)N_NODES * 128];
__device__ float g_h1 [(size_t)N_NODES * 128];
__device__ float g_hA [(size_t)N_NODES * 128];
__device__ float g_hB [(size_t)N_NODES * 128];
__device__ float g_zc [(size_t)N_NODES * 64];
__device__ float g_Wq1[128 * 512];
__device__ float g_Wq2[128 * 512];
__device__ float g_bq [512];
__device__ int   g_cnt   [N_NODES];
__device__ int   g_rowptr[N_NODES + 1];
__device__ int   g_cur   [N_NODES];
__device__ int   g_colidx[N_EDGES];

// ----------------- small utility kernels -----------------
__global__ void k_zero_f4(float4* p, int c4) {
    int i = blockIdx.x * blockDim.x + threadIdx.x;
    if (i < c4) p[i] = make_float4(0.f, 0.f, 0.f, 0.f);
}
__global__ void k_zero_i(int* p, int c) {
    int i = blockIdx.x * blockDim.x + threadIdx.x;
    if (i < c) p[i] = 0;
}
__global__ void k_hist(const int* __restrict__ dst, int e, int* __restrict__ cnt) {
    int i = blockIdx.x * blockDim.x + threadIdx.x;
    if (i < e) atomicAdd(&cnt[dst[i]], 1);
}
__global__ void k_copy_i(const int* __restrict__ a, int* __restrict__ b, int c) {
    int i = blockIdx.x * blockDim.x + threadIdx.x;
    if (i < c) b[i] = a[i];
}
__global__ void k_fill(const int* __restrict__ src, const int* __restrict__ dst, int e,
                       int* __restrict__ cur, int* __restrict__ colidx) {
    int i = blockIdx.x * blockDim.x + threadIdx.x;
    if (i < e) {
        int p = atomicAdd(&cur[dst[i]], 1);
        colidx[p] = src[i];
    }
}
// make neighbor order deterministic (atomic fill order varies run-to-run)
__global__ void k_sortseg(const int* __restrict__ rp, int* __restrict__ ci, int n) {
    int v = blockIdx.x * blockDim.x + threadIdx.x;
    if (v >= n) return;
    int s = rp[v], e = rp[v + 1];
    for (int i = s + 1; i < e; i++) {
        int key = ci[i];
        int j = i - 1;
        while (j >= s && ci[j] > key) { ci[j + 1] = ci[j]; j--; }
        ci[j + 1] = key;
    }
}

// single-block exclusive scan over n counts -> rowptr[0..n]
__global__ void k_scan(const int* __restrict__ cnt, int* __restrict__ rowptr, int n) {
    __shared__ int wsums[32];
    __shared__ int s_carry;
    int tid = threadIdx.x;
    int lane = tid & 31, wid = tid >> 5;
    if (tid == 0) s_carry = 0;
    __syncthreads();
    for (int base = 0; base < n; base += 1024) {
        int i = base + tid;
        int v = (i < n) ? cnt[i] : 0;
        int x = v;
#pragma unroll
        for (int o = 1; o < 32; o <<= 1) {
            int t = __shfl_up_sync(0xffffffffu, x, o);
            if (lane >= o) x += t;
        }
        if (lane == 31) wsums[wid] = x;
        __syncthreads();
        if (tid < 32) {
            int s = wsums[tid];
#pragma unroll
            for (int o = 1; o < 32; o <<= 1) {
                int t = __shfl_up_sync(0xffffffffu, s, o);
                if (tid >= o) s += t;
            }
            wsums[tid] = s;
        }
        __syncthreads();
        int incl = x + ((wid > 0) ? wsums[wid - 1] : 0);
        int excl = s_carry + incl - v;
        if (i < n) rowptr[i] = excl;
        int blocktot = wsums[31];
        __syncthreads();
        if (tid == 0) s_carry += blocktot;
        __syncthreads();
    }
    if (tid == 0) rowptr[n] = s_carry;
}

// rearrange GRU weights into gate quads: column 4j+g over OUT=512
//  g=0: r (Wih & Whh), g=1: z (Wih & Whh), g=2: n-input (Wih only), g=3: n-hidden (Whh only)
__global__ void k_prep_gru(const float* __restrict__ Wih, const float* __restrict__ Whh,
                           const float* __restrict__ bih, const float* __restrict__ bhh,
                           float* __restrict__ Wq1, float* __restrict__ Wq2, float* __restrict__ bq) {
    int idx = blockIdx.x * blockDim.x + threadIdx.x;
    if (idx >= 128 * 512) return;
    int k = idx >> 9, c = idx & 511, j = c >> 2, g = c & 3;
    float w1 = 0.f, w2 = 0.f;
    if (g == 0)      { w1 = Wih[j * 128 + k];         w2 = Whh[j * 128 + k]; }
    else if (g == 1) { w1 = Wih[(128 + j) * 128 + k]; w2 = Whh[(128 + j) * 128 + k]; }
    else if (g == 2) { w1 = Wih[(256 + j) * 128 + k]; }
    else             { w2 = Whh[(256 + j) * 128 + k]; }
    Wq1[idx] = w1;
    Wq2[idx] = w2;
    if (idx < 512) {
        int jj = idx >> 2, gg = idx & 3;
        bq[idx] = (gg == 0) ? bih[jj] + bhh[jj]
                : (gg == 1) ? bih[128 + jj] + bhh[128 + jj]
                : (gg == 2) ? bih[256 + jj]
                            : bhh[256 + jj];
    }
}

// ----------------- mean aggregation: warp per node (CSR gather) -----------------
__global__ void __launch_bounds__(256) k_agg64(const float* __restrict__ x, float* __restrict__ out,
                                               const int* __restrict__ rp, const int* __restrict__ ci, int n) {
    int w = (blockIdx.x * blockDim.x + threadIdx.x) >> 5;
    if (w >= n) return;
    int lane = threadIdx.x & 31;
    int s0 = rp[w], s1 = rp[w + 1];
    float ax = 0.f, ay = 0.f;
    int e = s0;
    for (; e + 4 <= s1; e += 4) {
        int i0 = ci[e], i1 = ci[e + 1], i2 = ci[e + 2], i3 = ci[e + 3];
        float2 v0 = *(const float2*)(x + (size_t)i0 * 64 + lane * 2);
        float2 v1 = *(const float2*)(x + (size_t)i1 * 64 + lane * 2);
        float2 v2 = *(const float2*)(x + (size_t)i2 * 64 + lane * 2);
        float2 v3 = *(const float2*)(x + (size_t)i3 * 64 + lane * 2);
        ax += (v0.x + v1.x) + (v2.x + v3.x);
        ay += (v0.y + v1.y) + (v2.y + v3.y);
    }
    for (; e < s1; e++) {
        int i0 = ci[e];
        float2 v0 = *(const float2*)(x + (size_t)i0 * 64 + lane * 2);
        ax += v0.x; ay += v0.y;
    }
    int d = s1 - s0; if (d < 1) d = 1;
    float inv = 1.f / (float)d;
    *(float2*)(out + (size_t)w * 64 + lane * 2) = make_float2(ax * inv, ay * inv);
}

__global__ void __launch_bounds__(256) k_agg128(const float* __restrict__ x, float* __restrict__ out,
                                                const int* __restrict__ rp, const int* __restrict__ ci, int n) {
    int w = (blockIdx.x * blockDim.x + threadIdx.x) >> 5;
    if (w >= n) return;
    int lane = threadIdx.x & 31;
    int s0 = rp[w], s1 = rp[w + 1];
    float4 acc = make_float4(0.f, 0.f, 0.f, 0.f);
    int e = s0;
    for (; e + 4 <= s1; e += 4) {
        int i0 = ci[e], i1 = ci[e + 1], i2 = ci[e + 2], i3 = ci[e + 3];
        float4 v0 = *(const float4*)(x + (size_t)i0 * 128 + lane * 4);
        float4 v1 = *(const float4*)(x + (size_t)i1 * 128 + lane * 4);
        float4 v2 = *(const float4*)(x + (size_t)i2 * 128 + lane * 4);
        float4 v3 = *(const float4*)(x + (size_t)i3 * 128 + lane * 4);
        acc.x += (v0.x + v1.x) + (v2.x + v3.x);
        acc.y += (v0.y + v1.y) + (v2.y + v3.y);
        acc.z += (v0.z + v1.z) + (v2.z + v3.z);
        acc.w += (v0.w + v1.w) + (v2.w + v3.w);
    }
    for (; e < s1; e++) {
        int i0 = ci[e];
        float4 v0 = *(const float4*)(x + (size_t)i0 * 128 + lane * 4);
        acc.x += v0.x; acc.y += v0.y; acc.z += v0.z; acc.w += v0.w;
    }
    int d = s1 - s0; if (d < 1) d = 1;
    float inv = 1.f / (float)d;
    *(float4*)(out + (size_t)w * 128 + lane * 4) =
        make_float4(acc.x * inv, acc.y * inv, acc.z * inv, acc.w * inv);
}

// ----------------- fused dual-input GEMM -----------------
// C[row, jbase+c] = epi( A1[row,:K1]@W1[:,jbase+c] + A2[row,:K2]@W2[:,jbase+c] + bias )
// EPI 0: LayerNorm+ReLU          (BN=128, full row in block, out stride 128)
// EPI 1: LayerNorm+ReLU+residual (res added after relu), out stride 128
// EPI 2: GRU gate-quad update    (OUT=512, grid.y=4; res = h_prev; writes h cols j)
// EPI 3: bias+ReLU store         (BN=64, out stride 64)
// thread map: tid = ty*16 + tx ; rows = blockIdx.x*64 + ty*4 + m ; cols = jbase + tx*TN + nn
template <int BN, int TN, int EPI>
__global__ void __launch_bounds__(256) k_gemm(
    const float* __restrict__ A1, int K1, const float* __restrict__ W1,
    const float* __restrict__ A2, int K2, const float* __restrict__ W2,
    int ldw,
    const float* __restrict__ bias, const float* __restrict__ gamma,
    const float* __restrict__ beta, const float* __restrict__ res,
    float* __restrict__ out, int n)
{
    __shared__ __align__(16) float As[16 * 64];
    __shared__ __align__(16) float Ws[16 * BN];

    int tid = threadIdx.x;
    int tx = tid & 15, ty = tid >> 4;
    int row0 = blockIdx.x * 64;
    int jbase = blockIdx.y * BN;

    float acc[4][TN];
#pragma unroll
    for (int m = 0; m < 4; m++)
#pragma unroll
        for (int nn = 0; nn < TN; nn++) acc[m][nn] = 0.f;

    for (int p = 0; p < 2; p++) {
        const float* A = p ? A2 : A1;
        const float* W = p ? W2 : W1;
        int K = p ? K2 : K1;
        if (K == 0) continue;
        for (int k0 = 0; k0 < K; k0 += 16) {
            // load A tile (64 rows x 16 cols), transposed into As[k][row]
            {
                int ra = tid >> 2, cs = tid & 3;
                int grow = row0 + ra;
                float4 v = make_float4(0.f, 0.f, 0.f, 0.f);
                if (grow < n) v = *(const float4*)(A + (size_t)grow * K + k0 + cs * 4);
                As[(cs * 4 + 0) * 64 + ra] = v.x;
                As[(cs * 4 + 1) * 64 + ra] = v.y;
                As[(cs * 4 + 2) * 64 + ra] = v.z;
                As[(cs * 4 + 3) * 64 + ra] = v.w;
            }
            // load W tile (16 x BN)
            constexpr int WLOAD = 16 * BN / 4;
#pragma unroll
            for (int idx = tid; idx < WLOAD; idx += 256) {
                int kr = idx / (BN / 4), cp = idx % (BN / 4);
                *(float4*)&Ws[kr * BN + cp * 4] =
                    *(const float4*)(W + (size_t)(k0 + kr) * ldw + jbase + cp * 4);
            }
            __syncthreads();
#pragma unroll
            for (int k = 0; k < 16; k++) {
                float4 a4 = *(float4*)&As[k * 64 + ty * 4];
                float am[4] = {a4.x, a4.y, a4.z, a4.w};
                float wv[TN];
#pragma unroll
                for (int nn = 0; nn < TN; nn += 4) {
                    float4 w4 = *(float4*)&Ws[k * BN + tx * TN + nn];
                    wv[nn] = w4.x; wv[nn + 1] = w4.y; wv[nn + 2] = w4.z; wv[nn + 3] = w4.w;
                }
#pragma unroll
                for (int m = 0; m < 4; m++)
#pragma unroll
                    for (int nn = 0; nn < TN; nn++)
                        acc[m][nn] = fmaf(am[m], wv[nn], acc[m][nn]);
            }
            __syncthreads();
        }
    }

    // ------------- epilogues -------------
    float bc[TN];
#pragma unroll
    for (int nn = 0; nn < TN; nn++) bc[nn] = bias[jbase + tx * TN + nn];

    if (EPI == 0 || EPI == 1) {
        float gc[TN], bec[TN];
#pragma unroll
        for (int nn = 0; nn < TN; nn++) {
            gc[nn] = gamma[jbase + tx * TN + nn];
            bec[nn] = beta[jbase + tx * TN + nn];
        }
#pragma unroll
        for (int m = 0; m < 4; m++) {
            float s = 0.f, sq = 0.f;
#pragma unroll
            for (int nn = 0; nn < TN; nn++) {
                float v = acc[m][nn] + bc[nn];
                acc[m][nn] = v;
                s += v; sq += v * v;
            }
#pragma unroll
            for (int o = 1; o < 16; o <<= 1) {
                s  += __shfl_xor_sync(0xffffffffu, s, o);
                sq += __shfl_xor_sync(0xffffffffu, sq, o);
            }
            float mean = s * (1.f / 128.f);
            float var = sq * (1.f / 128.f) - mean * mean;
            float rs = rsqrtf(var + 1e-5f);
            int grow = row0 + ty * 4 + m;
            if (grow < n) {
                float vout[TN];
#pragma unroll
                for (int nn = 0; nn < TN; nn++) {
                    float v = (acc[m][nn] - mean) * rs * gc[nn] + bec[nn];
                    v = fmaxf(v, 0.f);
                    if (EPI == 1) v += res[(size_t)grow * 128 + tx * TN + nn];
                    vout[nn] = v;
                }
#pragma unroll
                for (int nn = 0; nn < TN; nn += 4)
                    *(float4*)(out + (size_t)grow * 128 + tx * TN + nn) =
                        make_float4(vout[nn], vout[nn + 1], vout[nn + 2], vout[nn + 3]);
            }
        }
    } else if (EPI == 2) {
#pragma unroll
        for (int m = 0; m < 4; m++) {
            int grow = row0 + ty * 4 + m;
            if (grow < n) {
#pragma unroll
                for (int q = 0; q < TN / 4; q++) {
                    float cr = acc[m][q * 4 + 0] + bc[q * 4 + 0];
                    float cz = acc[m][q * 4 + 1] + bc[q * 4 + 1];
                    float ci_ = acc[m][q * 4 + 2] + bc[q * 4 + 2];
                    float ch = acc[m][q * 4 + 3] + bc[q * 4 + 3];
                    float r = 1.f / (1.f + expf(-cr));
                    float z = 1.f / (1.f + expf(-cz));
                    float ng = tanhf(ci_ + r * ch);
                    int j = ((jbase + tx * TN) >> 2) + q;
                    float hp = res[(size_t)grow * 128 + j];
                    out[(size_t)grow * 128 + j] = (1.f - z) * ng + z * hp;
                }
            }
        }
    } else {  // EPI == 3 : bias + relu
#pragma unroll
        for (int m = 0; m < 4; m++) {
            int grow = row0 + ty * 4 + m;
            if (grow < n) {
                float vout[TN];
#pragma unroll
                for (int nn = 0; nn < TN; nn++)
                    vout[nn] = fmaxf(acc[m][nn] + bc[nn], 0.f);
#pragma unroll
                for (int nn = 0; nn < TN; nn += 4)
                    *(float4*)(out + (size_t)grow * 64 + tx * TN + nn) =
                        make_float4(vout[nn], vout[nn + 1], vout[nn + 2], vout[nn + 3]);
            }
        }
    }
}

// final logits: warp per row, zc[64] @ W2[64,2] + b2
__global__ void __launch_bounds__(256) k_logits(const float* __restrict__ zc,
                                                const float* __restrict__ W2,
                                                const float* __restrict__ b2,
                                                float* __restrict__ out, int n) {
    int w = (blockIdx.x * blockDim.x + threadIdx.x) >> 5;
    if (w >= n) return;
    int lane = threadIdx.x & 31;
    float z0 = zc[(size_t)w * 64 + lane];
    float z1 = zc[(size_t)w * 64 + 32 + lane];
    float a0 = z0 * W2[lane * 2 + 0] + z1 * W2[(lane + 32) * 2 + 0];
    float a1 = z0 * W2[lane * 2 + 1] + z1 * W2[(lane + 32) * 2 + 1];
#pragma unroll
    for (int o = 16; o > 0; o >>= 1) {
        a0 += __shfl_xor_sync(0xffffffffu, a0, o);
        a1 += __shfl_xor_sync(0xffffffffu, a1, o);
    }
    if (lane == 0) {
        out[(size_t)w * 2 + 0] = a0 + b2[0];
        out[(size_t)w * 2 + 1] = a1 + b2[1];
    }
}

// ----------------- host launch -----------------
extern "C" void kernel_launch(void* const* d_in, const int* in_sizes, int n_in,
                              void* d_out, int out_size) {
    const int N = N_NODES, E = N_EDGES;

    // Identify inputs robustly (works for both setup-dict order and signature order):
    // x_seq and edge_index by unique element counts; the 18 weight tensors keep
    // their relative order in both orderings.
    const float* x_seq = nullptr;
    const int* eidx = nullptr;
    const float* Wt[18];
    int wi = 0;
    for (int i = 0; i < n_in; i++) {
        if (in_sizes[i] == 2 * E) eidx = (const int*)d_in[i];
        else if (in_sizes[i] == T_STEPS * N * 64) x_seq = (const float*)d_in[i];
        else if (wi < 18) Wt[wi++] = (const float*)d_in[i];
    }
    const float *Wn0 = Wt[0], *Ws0 = Wt[1], *b0 = Wt[2], *g0 = Wt[3], *be0 = Wt[4];
    const float *Wn1 = Wt[5], *Ws1 = Wt[6], *b1 = Wt[7], *g1 = Wt[8], *be1 = Wt[9];
    const float *gWih = Wt[10], *gWhh = Wt[11], *gbih = Wt[12], *gbhh = Wt[13];
    const float *cW1 = Wt[14], *cb1 = Wt[15], *cW2 = Wt[16], *cb2 = Wt[17];

    // scratch symbol addresses
    float *agg, *h0, *h1, *hA, *hB, *zc, *Wq1, *Wq2, *bq;
    int *cnt, *rp, *cur, *ci;
    cudaGetSymbolAddress((void**)&agg, g_agg);
    cudaGetSymbolAddress((void**)&h0, g_h0);
    cudaGetSymbolAddress((void**)&h1, g_h1);
    cudaGetSymbolAddress((void**)&hA, g_hA);
    cudaGetSymbolAddress((void**)&hB, g_hB);
    cudaGetSymbolAddress((void**)&zc, g_zc);
    cudaGetSymbolAddress((void**)&Wq1, g_Wq1);
    cudaGetSymbolAddress((void**)&Wq2, g_Wq2);
    cudaGetSymbolAddress((void**)&bq, g_bq);
    cudaGetSymbolAddress((void**)&cnt, g_cnt);
    cudaGetSymbolAddress((void**)&rp, g_rowptr);
    cudaGetSymbolAddress((void**)&cur, g_cur);
    cudaGetSymbolAddress((void**)&ci, g_colidx);

    const int* src = eidx;
    const int* dst = eidx + E;

    // ---- build CSR (deterministic after per-segment sort) ----
    k_zero_i<<<(N + 255) / 256, 256>>>(cnt, N);
    k_hist<<<(E + 255) / 256, 256>>>(dst, E, cnt);
    k_scan<<<1, 1024>>>(cnt, rp, N);
    k_copy_i<<<(N + 255) / 256, 256>>>(rp, cur, N);
    k_fill<<<(E + 255) / 256, 256>>>(src, dst, E, cur, ci);
    k_sortseg<<<(N + 255) / 256, 256>>>(rp, ci, N);

    // ---- init GRU state + rearranged weights ----
    k_zero_f4<<<(N * 128 / 4 + 255) / 256, 256>>>((float4*)hA, N * 128 / 4);
    k_prep_gru<<<(128 * 512 + 255) / 256, 256>>>(gWih, gWhh, gbih, gbhh, Wq1, Wq2, bq);

    const int GRID_M = (N + 63) / 64;        // 1563
    const int AGG_GRID = (N + 7) / 8;        // warp per node, 8 warps/block

    float* hprev = hA;
    float* hnext = hB;
    for (int t = 0; t < T_STEPS; t++) {
        const float* xt = x_seq + (size_t)t * N * 64;
        // SAGE layer 0
        k_agg64<<<AGG_GRID, 256>>>(xt, agg, rp, ci, N);
        k_gemm<128, 8, 0><<<dim3(GRID_M, 1), 256>>>(
            agg, 64, Wn0, xt, 64, Ws0, 128, b0, g0, be0, nullptr, h0, N);
        // SAGE layer 1 (+ residual)
        k_agg128<<<AGG_GRID, 256>>>(h0, agg, rp, ci, N);
        k_gemm<128, 8, 1><<<dim3(GRID_M, 1), 256>>>(
            agg, 128, Wn1, h0, 128, Ws1, 128, b1, g1, be1, h0, h1, N);
        // GRU step (gate-quad fused)
        k_gemm<128, 8, 2><<<dim3(GRID_M, 4), 256>>>(
            h1, 128, Wq1, hprev, 128, Wq2, 512, bq, nullptr, nullptr, hprev, hnext, N);
        float* tmp = hprev; hprev = hnext; hnext = tmp;
    }
    // classifier
    k_gemm<64, 4, 3><<<dim3(GRID_M, 1), 256>>>(
        hprev, 128, cW1, nullptr, 0, nullptr, 64, cb1, nullptr, nullptr, nullptr, zc, N);
    k_logits<<<AGG_GRID, 256>>>(zc, cW2, cb2, (float*)d_out, N);
}

// round 5
// speedup vs baseline: 1.7522x; 1.7522x over previous
#include <cuda_runtime.h>
#include <cuda_bf16.h>
#include <mma.h>
#include <cstdint>

using namespace nvcuda;

#define N_NODES 100000
#define N_EDGES 1600000
#define T_STEPS 12

// ----------------- static device scratch -----------------
__device__ float g_agg[(size_t)N_NODES * 128];
__device__ float g_h0 [(size_t)N_NODES * 128];
__device__ float g_h1 [(size_t)N_NODES * 128];
__device__ float g_hA [(size_t)N_NODES * 128];
__device__ float g_hB [(size_t)N_NODES * 128];
__device__ float g_zc [(size_t)N_NODES * 64];
__device__ float g_Wc0t[128 * 128];   // [N=128, K=128] = [Wn0 | Ws0]^T  (K-major)
__device__ float g_Wc1t[128 * 256];   // [N=128, K=256] = [Wn1 | Ws1]^T
__device__ float g_Wqt [512 * 256];   // [N=512 gate-quads, K=256]
__device__ float g_cW1t[64 * 128];    // [N=64, K=128]
__device__ float g_bq [512];
__device__ int   g_cnt   [N_NODES];
__device__ int   g_rowptr[N_NODES + 1];
__device__ int   g_cur   [N_NODES];
__device__ int   g_colidx[N_EDGES];

__device__ __forceinline__ float sigf(float x) { return 1.f / (1.f + expf(-x)); }

// store float4 as tf32-truncated floats
__device__ __forceinline__ void sts4_tf32(float* p, float4 v) {
    uint32_t r0, r1, r2, r3;
    asm("cvt.rn.tf32.f32 %0, %1;" : "=r"(r0) : "f"(v.x));
    asm("cvt.rn.tf32.f32 %0, %1;" : "=r"(r1) : "f"(v.y));
    asm("cvt.rn.tf32.f32 %0, %1;" : "=r"(r2) : "f"(v.z));
    asm("cvt.rn.tf32.f32 %0, %1;" : "=r"(r3) : "f"(v.w));
    *(uint4*)p = make_uint4(r0, r1, r2, r3);
}

// ----------------- wmma tf32 GEMM + fused epilogues -----------------
// D[row, jbase+c] = epi( A1[row,:K1]@Bt[jbase+c,:K1]^T + A2[row,:K2]@Bt[...,K1:]^T )
// Bt is [Ntot x Ktot] K-major. K consumed in chunks of 32.
// EPI 0: bias+LayerNorm+ReLU            (BM=64, BN=128, out stride 128)
// EPI 1: bias+LayerNorm+ReLU+residual   (BM=64, BN=128)
// EPI 2: GRU gate-quad update           (BM=64, BN=128, grid.y=4, res=h_prev)
// EPI 3: bias+ReLU                      (BM=128, BN=64, out stride 64)
template <int BM, int BN, int WR, int WC, int EPI>
__global__ void __launch_bounds__(256) k_wmma(
    const float* __restrict__ A1, int K1,
    const float* __restrict__ A2, int K2,
    const float* __restrict__ Bt, int Ktot,
    const float* __restrict__ bias,
    const float* __restrict__ gamma, const float* __restrict__ beta,
    const float* __restrict__ res,
    float* __restrict__ out, int n)
{
    constexpr int LDA = 40;            // 160B rows: 32B-aligned frag ptrs
    constexpr int LDB = 40;
    constexpr int LDC = BN + 8;        // 32B-aligned rows
    extern __shared__ __align__(32) float smem[];
    float* As = smem;
    float* Bs = smem + BM * LDA;
    float* Cs = smem;

    const int tid = threadIdx.x;
    const int wid = tid >> 5;
    const int wr = wid / WC, wc = wid % WC;
    const int row0 = blockIdx.x * BM;
    const int jbase = blockIdx.y * BN;

    wmma::fragment<wmma::accumulator, 16, 16, 8, float> acc[2][2];
#pragma unroll
    for (int i = 0; i < 2; i++)
#pragma unroll
        for (int j = 0; j < 2; j++) wmma::fill_fragment(acc[i][j], 0.f);

    const int nc = Ktot / 32;
    for (int c = 0; c < nc; c++) {
        int kg = c * 32;
        const float* Asrc; int Kph, koff;
        if (kg < K1) { Asrc = A1; Kph = K1; koff = kg; }
        else         { Asrc = A2; Kph = K2; koff = kg - K1; }
        // stage A tile (BM x 32) as tf32
#pragma unroll
        for (int idx = tid; idx < BM * 8; idx += 256) {
            int r = idx >> 3, q = idx & 7;
            int grow = row0 + r;
            float4 v = make_float4(0.f, 0.f, 0.f, 0.f);
            if (grow < n) v = *(const float4*)(Asrc + (size_t)grow * Kph + koff + q * 4);
            sts4_tf32(&As[r * LDA + q * 4], v);
        }
        // stage B tile (BN x 32) as tf32
#pragma unroll
        for (int idx = tid; idx < BN * 8; idx += 256) {
            int r = idx >> 3, q = idx & 7;
            float4 v = *(const float4*)(Bt + (size_t)(jbase + r) * Ktot + kg + q * 4);
            sts4_tf32(&Bs[r * LDB + q * 4], v);
        }
        __syncthreads();
#pragma unroll
        for (int ks = 0; ks < 4; ks++) {
            wmma::fragment<wmma::matrix_a, 16, 16, 8, wmma::precision::tf32, wmma::row_major> a0, a1;
            wmma::fragment<wmma::matrix_b, 16, 16, 8, wmma::precision::tf32, wmma::col_major> b0, b1;
            wmma::load_matrix_sync(a0, As + (wr * 32 +  0) * LDA + ks * 8, LDA);
            wmma::load_matrix_sync(a1, As + (wr * 32 + 16) * LDA + ks * 8, LDA);
            wmma::load_matrix_sync(b0, Bs + (wc * 32 +  0) * LDB + ks * 8, LDB);
            wmma::load_matrix_sync(b1, Bs + (wc * 32 + 16) * LDB + ks * 8, LDB);
            wmma::mma_sync(acc[0][0], a0, b0, acc[0][0]);
            wmma::mma_sync(acc[0][1], a0, b1, acc[0][1]);
            wmma::mma_sync(acc[1][0], a1, b0, acc[1][0]);
            wmma::mma_sync(acc[1][1], a1, b1, acc[1][1]);
        }
        __syncthreads();
    }

    // spill accumulators to smem C tile
#pragma unroll
    for (int i = 0; i < 2; i++)
#pragma unroll
        for (int j = 0; j < 2; j++)
            wmma::store_matrix_sync(Cs + (wr * 32 + i * 16) * LDC + wc * 32 + j * 16,
                                    acc[i][j], LDC, wmma::mem_row_major);
    __syncthreads();

    // ------------- epilogues -------------
    if constexpr (EPI == 0 || EPI == 1) {
        // 4 threads per row, 32 cols each; LN over 128 cols
        int r = tid >> 2, seg = tid & 3;
        int grow = row0 + r;
        float v[32];
        float sum = 0.f, sq = 0.f;
#pragma unroll
        for (int q = 0; q < 8; q++) {
            float4 c4 = *(float4*)&Cs[r * LDC + seg * 32 + q * 4];
            float b0v = __ldg(&bias[seg * 32 + q * 4 + 0]);
            float b1v = __ldg(&bias[seg * 32 + q * 4 + 1]);
            float b2v = __ldg(&bias[seg * 32 + q * 4 + 2]);
            float b3v = __ldg(&bias[seg * 32 + q * 4 + 3]);
            v[q * 4 + 0] = c4.x + b0v; v[q * 4 + 1] = c4.y + b1v;
            v[q * 4 + 2] = c4.z + b2v; v[q * 4 + 3] = c4.w + b3v;
#pragma unroll
            for (int u = 0; u < 4; u++) { sum += v[q * 4 + u]; sq += v[q * 4 + u] * v[q * 4 + u]; }
        }
        sum += __shfl_xor_sync(0xffffffffu, sum, 1);
        sq  += __shfl_xor_sync(0xffffffffu, sq, 1);
        sum += __shfl_xor_sync(0xffffffffu, sum, 2);
        sq  += __shfl_xor_sync(0xffffffffu, sq, 2);
        float mean = sum * (1.f / 128.f);
        float var = sq * (1.f / 128.f) - mean * mean;
        float rs = rsqrtf(var + 1e-5f);
        if (grow < n) {
#pragma unroll
            for (int q = 0; q < 8; q++) {
                int cc = seg * 32 + q * 4;
                float4 o;
                o.x = fmaxf((v[q * 4 + 0] - mean) * rs * __ldg(&gamma[cc + 0]) + __ldg(&beta[cc + 0]), 0.f);
                o.y = fmaxf((v[q * 4 + 1] - mean) * rs * __ldg(&gamma[cc + 1]) + __ldg(&beta[cc + 1]), 0.f);
                o.z = fmaxf((v[q * 4 + 2] - mean) * rs * __ldg(&gamma[cc + 2]) + __ldg(&beta[cc + 2]), 0.f);
                o.w = fmaxf((v[q * 4 + 3] - mean) * rs * __ldg(&gamma[cc + 3]) + __ldg(&beta[cc + 3]), 0.f);
                if (EPI == 1) {
                    float4 rv = *(const float4*)(res + (size_t)grow * 128 + cc);
                    o.x += rv.x; o.y += rv.y; o.z += rv.z; o.w += rv.w;
                }
                *(float4*)(out + (size_t)grow * 128 + cc) = o;
            }
        }
    } else if constexpr (EPI == 2) {
        // GRU gate quads: 128 gemm cols -> 32 h cols; 4 threads/row, 8 quads each
        int r = tid >> 2, seg = tid & 3;
        int grow = row0 + r;
        if (grow < n) {
            int lc0 = seg * 32;
            float hv[8];
#pragma unroll
            for (int q = 0; q < 8; q++) {
                int lc = lc0 + q * 4;
                int gcol = jbase + lc;
                float cr = Cs[r * LDC + lc + 0] + __ldg(&bias[gcol + 0]);
                float cz = Cs[r * LDC + lc + 1] + __ldg(&bias[gcol + 1]);
                float ci = Cs[r * LDC + lc + 2] + __ldg(&bias[gcol + 2]);
                float ch = Cs[r * LDC + lc + 3] + __ldg(&bias[gcol + 3]);
                float rg = sigf(cr);
                float z = sigf(cz);
                float ng = tanhf(ci + rg * ch);
                float hp = res[(size_t)grow * 128 + ((jbase + lc0) >> 2) + q];
                hv[q] = (1.f - z) * ng + z * hp;
            }
            int j0 = ((jbase + lc0) >> 2);
            *(float4*)(out + (size_t)grow * 128 + j0) = make_float4(hv[0], hv[1], hv[2], hv[3]);
            *(float4*)(out + (size_t)grow * 128 + j0 + 4) = make_float4(hv[4], hv[5], hv[6], hv[7]);
        }
    } else {  // EPI == 3: bias+relu, BN=64, out stride 64
        int r = tid >> 1, seg = tid & 1;
        int grow = row0 + r;
        if (grow < n) {
#pragma unroll
            for (int q = 0; q < 8; q++) {
                int cc = seg * 32 + q * 4;
                float4 c4 = *(float4*)&Cs[r * LDC + cc];
                float4 o;
                o.x = fmaxf(c4.x + __ldg(&bias[cc + 0]), 0.f);
                o.y = fmaxf(c4.y + __ldg(&bias[cc + 1]), 0.f);
                o.z = fmaxf(c4.z + __ldg(&bias[cc + 2]), 0.f);
                o.w = fmaxf(c4.w + __ldg(&bias[cc + 3]), 0.f);
                *(float4*)(out + (size_t)grow * 64 + cc) = o;
            }
        }
    }
}

// ----------------- CSR build + misc -----------------
__global__ void k_zero_f4(float4* p, int c4) {
    int i = blockIdx.x * blockDim.x + threadIdx.x;
    if (i < c4) p[i] = make_float4(0.f, 0.f, 0.f, 0.f);
}
__global__ void k_zero_i(int* p, int c) {
    int i = blockIdx.x * blockDim.x + threadIdx.x;
    if (i < c) p[i] = 0;
}
__global__ void k_hist(const int* __restrict__ dst, int e, int* __restrict__ cnt) {
    int i = blockIdx.x * blockDim.x + threadIdx.x;
    if (i < e) atomicAdd(&cnt[dst[i]], 1);
}
__global__ void k_copy_i(const int* __restrict__ a, int* __restrict__ b, int c) {
    int i = blockIdx.x * blockDim.x + threadIdx.x;
    if (i < c) b[i] = a[i];
}
__global__ void k_fill(const int* __restrict__ src, const int* __restrict__ dst, int e,
                       int* __restrict__ cur, int* __restrict__ colidx) {
    int i = blockIdx.x * blockDim.x + threadIdx.x;
    if (i < e) {
        int p = atomicAdd(&cur[dst[i]], 1);
        colidx[p] = src[i];
    }
}
__global__ void k_sortseg(const int* __restrict__ rp, int* __restrict__ ci, int n) {
    int v = blockIdx.x * blockDim.x + threadIdx.x;
    if (v >= n) return;
    int s = rp[v], e = rp[v + 1];
    for (int i = s + 1; i < e; i++) {
        int key = ci[i];
        int j = i - 1;
        while (j >= s && ci[j] > key) { ci[j + 1] = ci[j]; j--; }
        ci[j + 1] = key;
    }
}
__global__ void k_scan(const int* __restrict__ cnt, int* __restrict__ rowptr, int n) {
    __shared__ int wsums[32];
    __shared__ int s_carry;
    int tid = threadIdx.x;
    int lane = tid & 31, wid = tid >> 5;
    if (tid == 0) s_carry = 0;
    __syncthreads();
    for (int base = 0; base < n; base += 1024) {
        int i = base + tid;
        int v = (i < n) ? cnt[i] : 0;
        int x = v;
#pragma unroll
        for (int o = 1; o < 32; o <<= 1) {
            int t = __shfl_up_sync(0xffffffffu, x, o);
            if (lane >= o) x += t;
        }
        if (lane == 31) wsums[wid] = x;
        __syncthreads();
        if (tid < 32) {
            int s = wsums[tid];
#pragma unroll
            for (int o = 1; o < 32; o <<= 1) {
                int t = __shfl_up_sync(0xffffffffu, s, o);
                if (tid >= o) s += t;
            }
            wsums[tid] = s;
        }
        __syncthreads();
        int incl = x + ((wid > 0) ? wsums[wid - 1] : 0);
        int excl = s_carry + incl - v;
        if (i < n) rowptr[i] = excl;
        int blocktot = wsums[31];
        __syncthreads();
        if (tid == 0) s_carry += blocktot;
        __syncthreads();
    }
    if (tid == 0) rowptr[n] = s_carry;
}

// ----------------- weight pre-transpose kernels -----------------
__global__ void k_prep_c0(const float* __restrict__ Wn, const float* __restrict__ Ws,
                          float* __restrict__ o) {
    int idx = blockIdx.x * blockDim.x + threadIdx.x;
    if (idx >= 128 * 128) return;
    int nn = idx >> 7, k = idx & 127;
    o[idx] = (k < 64) ? Wn[k * 128 + nn] : Ws[(k - 64) * 128 + nn];
}
__global__ void k_prep_c1(const float* __restrict__ Wn, const float* __restrict__ Ws,
                          float* __restrict__ o) {
    int idx = blockIdx.x * blockDim.x + threadIdx.x;
    if (idx >= 128 * 256) return;
    int nn = idx >> 8, k = idx & 255;
    o[idx] = (k < 128) ? Wn[k * 128 + nn] : Ws[(k - 128) * 128 + nn];
}
__global__ void k_prep_qt(const float* __restrict__ Wih, const float* __restrict__ Whh,
                          const float* __restrict__ bih, const float* __restrict__ bhh,
                          float* __restrict__ o, float* __restrict__ bq) {
    int idx = blockIdx.x * blockDim.x + threadIdx.x;
    if (idx >= 512 * 256) return;
    int c = idx >> 8, k = idx & 255;
    int j = c >> 2, g = c & 3;
    float w = 0.f;
    if (k < 128) {
        if (g == 0)      w = Wih[j * 128 + k];
        else if (g == 1) w = Wih[(128 + j) * 128 + k];
        else if (g == 2) w = Wih[(256 + j) * 128 + k];
    } else {
        int kk = k - 128;
        if (g == 0)      w = Whh[j * 128 + kk];
        else if (g == 1) w = Whh[(128 + j) * 128 + kk];
        else if (g == 3) w = Whh[(256 + j) * 128 + kk];
    }
    o[idx] = w;
    if (idx < 512) {
        int jj = idx >> 2, gg = idx & 3;
        bq[idx] = (gg == 0) ? bih[jj] + bhh[jj]
                : (gg == 1) ? bih[128 + jj] + bhh[128 + jj]
                : (gg == 2) ? bih[256 + jj]
                            : bhh[256 + jj];
    }
}
__global__ void k_prep_cls(const float* __restrict__ W, float* __restrict__ o) {
    int idx = blockIdx.x * blockDim.x + threadIdx.x;
    if (idx >= 64 * 128) return;
    int oo = idx >> 7, k = idx & 127;
    o[idx] = W[k * 64 + oo];
}

// ----------------- mean aggregation (warp per node) -----------------
__global__ void __launch_bounds__(256) k_agg64(const float* __restrict__ x, float* __restrict__ out,
                                               const int* __restrict__ rp, const int* __restrict__ ci, int n) {
    int w = (blockIdx.x * blockDim.x + threadIdx.x) >> 5;
    if (w >= n) return;
    int lane = threadIdx.x & 31;
    int s0 = rp[w], s1 = rp[w + 1];
    float ax = 0.f, ay = 0.f;
    int e = s0;
    for (; e + 4 <= s1; e += 4) {
        int i0 = ci[e], i1 = ci[e + 1], i2 = ci[e + 2], i3 = ci[e + 3];
        float2 v0 = *(const float2*)(x + (size_t)i0 * 64 + lane * 2);
        float2 v1 = *(const float2*)(x + (size_t)i1 * 64 + lane * 2);
        float2 v2 = *(const float2*)(x + (size_t)i2 * 64 + lane * 2);
        float2 v3 = *(const float2*)(x + (size_t)i3 * 64 + lane * 2);
        ax += (v0.x + v1.x) + (v2.x + v3.x);
        ay += (v0.y + v1.y) + (v2.y + v3.y);
    }
    for (; e < s1; e++) {
        int i0 = ci[e];
        float2 v0 = *(const float2*)(x + (size_t)i0 * 64 + lane * 2);
        ax += v0.x; ay += v0.y;
    }
    int d = s1 - s0; if (d < 1) d = 1;
    float inv = 1.f / (float)d;
    *(float2*)(out + (size_t)w * 64 + lane * 2) = make_float2(ax * inv, ay * inv);
}
__global__ void __launch_bounds__(256) k_agg128(const float* __restrict__ x, float* __restrict__ out,
                                                const int* __restrict__ rp, const int* __restrict__ ci, int n) {
    int w = (blockIdx.x * blockDim.x + threadIdx.x) >> 5;
    if (w >= n) return;
    int lane = threadIdx.x & 31;
    int s0 = rp[w], s1 = rp[w + 1];
    float4 acc = make_float4(0.f, 0.f, 0.f, 0.f);
    int e = s0;
    for (; e + 4 <= s1; e += 4) {
        int i0 = ci[e], i1 = ci[e + 1], i2 = ci[e + 2], i3 = ci[e + 3];
        float4 v0 = *(const float4*)(x + (size_t)i0 * 128 + lane * 4);
        float4 v1 = *(const float4*)(x + (size_t)i1 * 128 + lane * 4);
        float4 v2 = *(const float4*)(x + (size_t)i2 * 128 + lane * 4);
        float4 v3 = *(const float4*)(x + (size_t)i3 * 128 + lane * 4);
        acc.x += (v0.x + v1.x) + (v2.x + v3.x);
        acc.y += (v0.y + v1.y) + (v2.y + v3.y);
        acc.z += (v0.z + v1.z) + (v2.z + v3.z);
        acc.w += (v0.w + v1.w) + (v2.w + v3.w);
    }
    for (; e < s1; e++) {
        int i0 = ci[e];
        float4 v0 = *(const float4*)(x + (size_t)i0 * 128 + lane * 4);
        acc.x += v0.x; acc.y += v0.y; acc.z += v0.z; acc.w += v0.w;
    }
    int d = s1 - s0; if (d < 1) d = 1;
    float inv = 1.f / (float)d;
    *(float4*)(out + (size_t)w * 128 + lane * 4) =
        make_float4(acc.x * inv, acc.y * inv, acc.z * inv, acc.w * inv);
}

// final logits: warp per row, zc[64] @ W2[64,2] + b2
__global__ void __launch_bounds__(256) k_logits(const float* __restrict__ zc,
                                                const float* __restrict__ W2,
                                                const float* __restrict__ b2,
                                                float* __restrict__ out, int n) {
    int w = (blockIdx.x * blockDim.x + threadIdx.x) >> 5;
    if (w >= n) return;
    int lane = threadIdx.x & 31;
    float z0 = zc[(size_t)w * 64 + lane];
    float z1 = zc[(size_t)w * 64 + 32 + lane];
    float a0 = z0 * W2[lane * 2 + 0] + z1 * W2[(lane + 32) * 2 + 0];
    float a1 = z0 * W2[lane * 2 + 1] + z1 * W2[(lane + 32) * 2 + 1];
#pragma unroll
    for (int o = 16; o > 0; o >>= 1) {
        a0 += __shfl_xor_sync(0xffffffffu, a0, o);
        a1 += __shfl_xor_sync(0xffffffffu, a1, o);
    }
    if (lane == 0) {
        out[(size_t)w * 2 + 0] = a0 + b2[0];
        out[(size_t)w * 2 + 1] = a1 + b2[1];
    }
}

// ----------------- host launch -----------------
extern "C" void kernel_launch(void* const* d_in, const int* in_sizes, int n_in,
                              void* d_out, int out_size) {
    const int N = N_NODES, E = N_EDGES;

    const float* x_seq = nullptr;
    const int* eidx = nullptr;
    const float* Wt[18];
    int wi = 0;
    for (int i = 0; i < n_in; i++) {
        if (in_sizes[i] == 2 * E) eidx = (const int*)d_in[i];
        else if (in_sizes[i] == T_STEPS * N * 64) x_seq = (const float*)d_in[i];
        else if (wi < 18) Wt[wi++] = (const float*)d_in[i];
    }
    const float *Wn0 = Wt[0], *Ws0 = Wt[1], *b0 = Wt[2], *g0 = Wt[3], *be0 = Wt[4];
    const float *Wn1 = Wt[5], *Ws1 = Wt[6], *b1 = Wt[7], *g1 = Wt[8], *be1 = Wt[9];
    const float *gWih = Wt[10], *gWhh = Wt[11], *gbih = Wt[12], *gbhh = Wt[13];
    const float *cW1 = Wt[14], *cb1 = Wt[15], *cW2 = Wt[16], *cb2 = Wt[17];

    float *agg, *h0, *h1, *hA, *hB, *zc, *Wc0t, *Wc1t, *Wqt, *cW1t, *bq;
    int *cnt, *rp, *cur, *ci;
    cudaGetSymbolAddress((void**)&agg, g_agg);
    cudaGetSymbolAddress((void**)&h0, g_h0);
    cudaGetSymbolAddress((void**)&h1, g_h1);
    cudaGetSymbolAddress((void**)&hA, g_hA);
    cudaGetSymbolAddress((void**)&hB, g_hB);
    cudaGetSymbolAddress((void**)&zc, g_zc);
    cudaGetSymbolAddress((void**)&Wc0t, g_Wc0t);
    cudaGetSymbolAddress((void**)&Wc1t, g_Wc1t);
    cudaGetSymbolAddress((void**)&Wqt, g_Wqt);
    cudaGetSymbolAddress((void**)&cW1t, g_cW1t);
    cudaGetSymbolAddress((void**)&bq, g_bq);
    cudaGetSymbolAddress((void**)&cnt, g_cnt);
    cudaGetSymbolAddress((void**)&rp, g_rowptr);
    cudaGetSymbolAddress((void**)&cur, g_cur);
    cudaGetSymbolAddress((void**)&ci, g_colidx);

    const int* src = eidx;
    const int* dst = eidx + E;

    // dynamic smem sizes: stage = BM*40 + BN*40 floats; epi = BM*(BN+8) floats
    const int SMA = (64 * 40 + 128 * 40) * 4;            // 30720 B
    const int SMC = (64 * 136) * 4;                      // 34816 B
    const int SM_A = SMA > SMC ? SMA : SMC;              // 34816
    const int SMA3 = (128 * 40 + 64 * 40) * 4;           // 30720
    const int SMC3 = (128 * 72) * 4;                     // 36864
    const int SM_B = SMA3 > SMC3 ? SMA3 : SMC3;          // 36864
    cudaFuncSetAttribute((const void*)k_wmma<64, 128, 2, 4, 0>, cudaFuncAttributeMaxDynamicSharedMemorySize, SM_A);
    cudaFuncSetAttribute((const void*)k_wmma<64, 128, 2, 4, 1>, cudaFuncAttributeMaxDynamicSharedMemorySize, SM_A);
    cudaFuncSetAttribute((const void*)k_wmma<64, 128, 2, 4, 2>, cudaFuncAttributeMaxDynamicSharedMemorySize, SM_A);
    cudaFuncSetAttribute((const void*)k_wmma<128, 64, 4, 2, 3>, cudaFuncAttributeMaxDynamicSharedMemorySize, SM_B);

    // ---- build CSR (deterministic after per-segment sort) ----
    k_zero_i<<<(N + 255) / 256, 256>>>(cnt, N);
    k_hist<<<(E + 255) / 256, 256>>>(dst, E, cnt);
    k_scan<<<1, 1024>>>(cnt, rp, N);
    k_copy_i<<<(N + 255) / 256, 256>>>(rp, cur, N);
    k_fill<<<(E + 255) / 256, 256>>>(src, dst, E, cur, ci);
    k_sortseg<<<(N + 255) / 256, 256>>>(rp, ci, N);

    // ---- init GRU state + pre-transposed weights ----
    k_zero_f4<<<(N * 128 / 4 + 255) / 256, 256>>>((float4*)hA, N * 128 / 4);
    k_prep_c0<<<(128 * 128 + 255) / 256, 256>>>(Wn0, Ws0, Wc0t);
    k_prep_c1<<<(128 * 256 + 255) / 256, 256>>>(Wn1, Ws1, Wc1t);
    k_prep_qt<<<(512 * 256 + 255) / 256, 256>>>(gWih, gWhh, gbih, gbhh, Wqt, bq);
    k_prep_cls<<<(64 * 128 + 255) / 256, 256>>>(cW1, cW1t);

    const int GRID64  = (N + 63) / 64;    // 1563 (BM=64 kernels)
    const int GRID128 = (N + 127) / 128;  // 782  (BM=128 classifier)
    const int AGG_GRID = (N + 7) / 8;

    float* hprev = hA;
    float* hnext = hB;
    for (int t = 0; t < T_STEPS; t++) {
        const float* xt = x_seq + (size_t)t * N * 64;
        // SAGE layer 0: LN+ReLU
        k_agg64<<<AGG_GRID, 256>>>(xt, agg, rp, ci, N);
        k_wmma<64, 128, 2, 4, 0><<<dim3(GRID64, 1), 256, SM_A>>>(
            agg, 64, xt, 64, Wc0t, 128, b0, g0, be0, nullptr, h0, N);
        // SAGE layer 1: LN+ReLU + residual(h0)
        k_agg128<<<AGG_GRID, 256>>>(h0, agg, rp, ci, N);
        k_wmma<64, 128, 2, 4, 1><<<dim3(GRID64, 1), 256, SM_A>>>(
            agg, 128, h0, 128, Wc1t, 256, b1, g1, be1, h0, h1, N);
        // GRU step (gate-quad epilogue), Ntot=512 in 4 col-blocks
        k_wmma<64, 128, 2, 4, 2><<<dim3(GRID64, 4), 256, SM_A>>>(
            h1, 128, hprev, 128, Wqt, 256, bq, nullptr, nullptr, hprev, hnext, N);
        float* tmp = hprev; hprev = hnext; hnext = tmp;
    }
    // classifier
    k_wmma<128, 64, 4, 2, 3><<<dim3(GRID128, 1), 256, SM_B>>>(
        hprev, 128, nullptr, 0, cW1t, 128, cb1, nullptr, nullptr, nullptr, zc, N);
    k_logits<<<AGG_GRID, 256>>>(zc, cW2, cb2, (float*)d_out, N);
}